// round 1
// baseline (speedup 1.0000x reference)
#include <cuda_runtime.h>
#include <cuda_bf16.h>
#include <cstdint>

// Problem constants
#define NB 16
#define NT_ 2048
#define ND 100
#define NG 2
#define NQ 4
#define NK 1024
#define DG 50
#define CD 50
#define NTOK (NB * NT_)          // 32768
#define TILE_T 64
#define NTILES (NTOK / TILE_T)   // 512
#define KTILE 128
#define NKT (NK / KTILE)         // 8

// Output layout (flattened tuple: quantized, loss, commit_losses, recon_loss)
#define OFF_QUANT 0
#define OFF_LOSS  (NTOK * ND)            // 3276800
#define OFF_COMMIT (OFF_LOSS + NTOK)     // 3309568
#define OFF_RECON  (OFF_COMMIT + 1)      // 3309569

// Scratch (device globals: no allocation allowed)
__device__ float g_cbT[NG * NQ * CD * NK];   // c-major transposed codebooks
__device__ float g_cc[NG * NQ * NK];         // ||cb_k||^2
__device__ float g_commit[NG * NQ];          // commit-loss accumulators

// Packed fp32x2 FMA (Blackwell FFMA2 — 2 FMAs per issue slot)
__device__ __forceinline__ void ffma2(unsigned long long& d,
                                      unsigned long long a,
                                      unsigned long long b) {
    asm("fma.rn.f32x2 %0, %1, %2, %0;" : "+l"(d) : "l"(a), "l"(b));
}

// ---------------------------------------------------------------------------
// Prep 1: transpose codebooks [g][q][k][c] -> [gq][c][k] (coalesced writes)
// ---------------------------------------------------------------------------
__global__ void prep_transpose(const float* __restrict__ cbsrc) {
    int idx = blockIdx.x * 256 + threadIdx.x;           // < 409600
    int gq = idx / (CD * NK);
    int rem = idx % (CD * NK);
    int c = rem / NK;
    int k = rem % NK;
    g_cbT[idx] = cbsrc[(size_t)gq * (NK * CD) + (size_t)k * CD + c];
}

// ---------------------------------------------------------------------------
// Prep 2: code norms ||cb||^2 + zero commit accumulators
// ---------------------------------------------------------------------------
__global__ void prep_cc() {
    int gid = blockIdx.x * 256 + threadIdx.x;           // < 8192
    if (gid < NG * NQ) g_commit[gid] = 0.0f;
    int gq = gid >> 10;
    int k = gid & (NK - 1);
    const float* base = g_cbT + (size_t)gq * (CD * NK) + k;
    float s = 0.0f;
#pragma unroll 10
    for (int c = 0; c < CD; c++) {
        float v = base[c * NK];
        s += v * v;
    }
    g_cc[gid] = s;
}

// ---------------------------------------------------------------------------
// Main RVQ kernel: block = 64 tokens x 1 group. Fused project_in, 4 residual
// VQ stages (distance GEMM + argmin + residual update), project_out.
// Shared layout (floats):
//   xs  [0,3200)        : x tile [64][50]
//   r2  [3200,9600)     : residual, duplicated float2, layout [c][tok]
//   qs  [9600,12800)    : sum of selected code vectors, [c][tok]
//   cbs [12800,19200)   : codebook k-tile, [c 50][k 128]
//   ccs [19200,20224)   : ||cb||^2 for current stage
// ---------------------------------------------------------------------------
#define SMEM_FLOATS 20224
#define SMEM_BYTES (SMEM_FLOATS * 4)

__global__ void __launch_bounds__(256)
rvq_main(const float* __restrict__ x,
         const float* __restrict__ W_in,
         const float* __restrict__ b_in,
         const float* __restrict__ W_out,
         const float* __restrict__ b_out,
         float* __restrict__ out) {
    extern __shared__ float smem[];
    float*  xs  = smem;
    float2* r2  = reinterpret_cast<float2*>(smem + 3200);
    float*  qs  = smem + 9600;
    float*  cbs = smem + 12800;
    float*  ccs = smem + 19200;

    const int tid = threadIdx.x;
    const int tx = tid & 15;          // 0..15 -> 8 codes each
    const int ty = tid >> 4;          // 0..15 -> 4 tokens each
    const int g = blockIdx.y;
    const int t0 = blockIdx.x * TILE_T;

    // ---- load x tile ----
    for (int i = tid; i < TILE_T * DG; i += 256) {
        int tok = i / DG, c = i % DG;
        xs[i] = x[(size_t)(t0 + tok) * ND + g * DG + c];
    }
    __syncthreads();

    // ---- project_in: r = x @ W_in + b_in; store duplicated; zero qs ----
    for (int i = tid; i < TILE_T * CD; i += 256) {
        int tok = i / CD, c = i % CD;
        float s = b_in[g * CD + c];
        const float* xrow = xs + tok * DG;
        const float* w = W_in + (size_t)(g * DG) * CD + c;
#pragma unroll 10
        for (int d = 0; d < DG; d++) s += xrow[d] * w[d * CD];
        r2[c * TILE_T + tok] = make_float2(s, s);
        qs[c * TILE_T + tok] = 0.0f;
    }

    const float2* r2base = r2 + ty * 4;
    const float*  cbbase = cbs + tx * 8;

    // ---- residual VQ stages ----
    for (int q = 0; q < NQ; q++) {
        const float* cbT_gq = g_cbT + (size_t)(g * NQ + q) * (CD * NK);
        __syncthreads();   // prior stage updates & prior cbs usage complete
        for (int i = tid; i < NK; i += 256)
            ccs[i] = g_cc[(g * NQ + q) * NK + i];

        float bestv[4];
        int   besti[4];
#pragma unroll
        for (int t = 0; t < 4; t++) { bestv[t] = __int_as_float(0x7f800000); besti[t] = 0; }

        for (int kt = 0; kt < NKT; kt++) {
            __syncthreads();
            for (int i = tid; i < CD * KTILE; i += 256) {
                int c = i >> 7, kk = i & 127;
                cbs[i] = cbT_gq[c * NK + (kt << 7) + kk];
            }
            __syncthreads();

            unsigned long long acc[16];
#pragma unroll
            for (int i = 0; i < 16; i++) acc[i] = 0ULL;

#pragma unroll 10
            for (int c = 0; c < CD; c++) {
                ulonglong2 ra = *reinterpret_cast<const ulonglong2*>(r2base + c * TILE_T);
                ulonglong2 rb = *reinterpret_cast<const ulonglong2*>(r2base + c * TILE_T + 2);
                ulonglong2 ca = *reinterpret_cast<const ulonglong2*>(cbbase + c * KTILE);
                ulonglong2 cb2 = *reinterpret_cast<const ulonglong2*>(cbbase + c * KTILE + 4);
                unsigned long long rr[4] = {ra.x, ra.y, rb.x, rb.y};
                unsigned long long cc4[4] = {ca.x, ca.y, cb2.x, cb2.y};
#pragma unroll
                for (int t = 0; t < 4; t++) {
#pragma unroll
                    for (int p = 0; p < 4; p++) ffma2(acc[t * 4 + p], rr[t], cc4[p]);
                }
            }

            // distances + running argmin (ascending k, strict < keeps first min)
#pragma unroll
            for (int t = 0; t < 4; t++) {
#pragma unroll
                for (int p = 0; p < 4; p++) {
                    float2 v = *reinterpret_cast<float2*>(&acc[t * 4 + p]);
                    int k0 = (kt << 7) + tx * 8 + p * 2;
                    float d0 = ccs[k0] - 2.0f * v.x;
                    float d1 = ccs[k0 + 1] - 2.0f * v.y;
                    if (d0 < bestv[t]) { bestv[t] = d0; besti[t] = k0; }
                    if (d1 < bestv[t]) { bestv[t] = d1; besti[t] = k0 + 1; }
                }
            }
        }

        // cross-lane argmin over the 16 tx lanes (lexicographic: first min wins)
#pragma unroll
        for (int off = 1; off < 16; off <<= 1) {
#pragma unroll
            for (int t = 0; t < 4; t++) {
                float ov = __shfl_xor_sync(0xffffffffu, bestv[t], off);
                int   oi = __shfl_xor_sync(0xffffffffu, besti[t], off);
                if (ov < bestv[t] || (ov == bestv[t] && oi < besti[t])) {
                    bestv[t] = ov; besti[t] = oi;
                }
            }
        }

        // residual update + commit accumulation (thread owns (its 4 tokens) x (c = tx+16m))
        float clocal = 0.0f;
#pragma unroll
        for (int t = 0; t < 4; t++) {
            int tok = ty * 4 + t;
            int idx = besti[t];
            for (int c = tx; c < CD; c += 16) {
                float qv = cbT_gq[c * NK + idx];
                float r = r2[c * TILE_T + tok].x;
                float dr = qv - r;
                clocal += dr * dr;
                float rn = r - qv;
                r2[c * TILE_T + tok] = make_float2(rn, rn);
                qs[c * TILE_T + tok] += qv;
            }
        }
        // warp-sum commit partials, one atomic per warp
#pragma unroll
        for (int off = 16; off; off >>= 1)
            clocal += __shfl_down_sync(0xffffffffu, clocal, off);
        if ((tid & 31) == 0) atomicAdd(&g_commit[g * NQ + q], clocal);
    }

    __syncthreads();

    // ---- project_out: out = qsum @ W_out + b_out ----
    for (int i = tid; i < TILE_T * DG; i += 256) {
        int tok = i / DG, dcol = i % DG;
        float s = b_out[g * DG + dcol];
        const float* w = W_out + (size_t)(g * CD) * DG + dcol;
#pragma unroll 10
        for (int c = 0; c < CD; c++) s += qs[c * TILE_T + tok] * w[c * DG];
        out[(size_t)(t0 + tok) * ND + g * DG + dcol] = s;
    }
}

// ---------------------------------------------------------------------------
// Finalize: recon_loss, loss, commit_losses scalar. Warp per token.
// ---------------------------------------------------------------------------
__global__ void __launch_bounds__(256)
finalize_kernel(const float* __restrict__ x, float* dst) {
    int w = (blockIdx.x * blockDim.x + threadIdx.x) >> 5;
    int lane = threadIdx.x & 31;

    float csum = 0.0f;
#pragma unroll
    for (int i = 0; i < NG * NQ; i++) csum += g_commit[i];
    float commit = csum * (1.0f / ((float)NTOK * (float)CD * (float)(NG * NQ)));

    if (w < NTOK) {
        const float* xr = x + (size_t)w * ND;
        const float* qr = dst + OFF_QUANT + (size_t)w * ND;
        float s = 0.0f;
        for (int d = lane; d < ND; d += 32) {
            float df = xr[d] - qr[d];
            s += df * df;
        }
#pragma unroll
        for (int off = 16; off; off >>= 1)
            s += __shfl_down_sync(0xffffffffu, s, off);
        if (lane == 0) {
            float recon = s * (1.0f / (float)ND);
            dst[OFF_RECON + w] = recon;
            dst[OFF_LOSS + w] = recon + commit;
        }
    }
    if (blockIdx.x == 0 && threadIdx.x == 0) dst[OFF_COMMIT] = commit;
}

// ---------------------------------------------------------------------------
extern "C" void kernel_launch(void* const* d_in, const int* in_sizes, int n_in,
                              void* d_out, int out_size) {
    const float* x      = (const float*)d_in[0];
    const float* W_in   = (const float*)d_in[1];
    const float* b_in   = (const float*)d_in[2];
    const float* W_out  = (const float*)d_in[3];
    const float* b_out  = (const float*)d_in[4];
    const float* cbooks = (const float*)d_in[5];
    float* out = (float*)d_out;

    cudaFuncSetAttribute(rvq_main, cudaFuncAttributeMaxDynamicSharedMemorySize,
                         SMEM_BYTES);

    prep_transpose<<<(NG * NQ * CD * NK) / 256, 256>>>(cbooks);
    prep_cc<<<(NG * NQ * NK) / 256, 256>>>();
    rvq_main<<<dim3(NTILES, NG), 256, SMEM_BYTES>>>(x, W_in, b_in, W_out, b_out, out);
    finalize_kernel<<<(NTOK * 32) / 256, 256>>>(x, out);
}

// round 2
// speedup vs baseline: 1.6383x; 1.6383x over previous
#include <cuda_runtime.h>
#include <cuda_bf16.h>
#include <cstdint>

// Problem constants
#define NB 16
#define NT_ 2048
#define ND 100
#define NG 2
#define NQ 4
#define NK 1024
#define DG 50
#define CD 50
#define NTOK (NB * NT_)          // 32768
#define TILE_T 128
#define NTILES (NTOK / TILE_T)   // 256
#define KTILE 256
#define NKT (NK / KTILE)         // 4

// Output layout (flattened tuple: quantized, loss, commit_losses, recon_loss)
#define OFF_QUANT 0
#define OFF_LOSS  (NTOK * ND)            // 3276800
#define OFF_COMMIT (OFF_LOSS + NTOK)     // 3309568
#define OFF_RECON  (OFF_COMMIT + 1)      // 3309569

// Scratch (device globals: no allocation allowed)
__device__ float g_cbT[NG * NQ * CD * NK];   // c-major transposed codebooks
__device__ float g_cc[NG * NQ * NK];         // ||cb_k||^2
__device__ float g_commit[NG * NQ];          // commit-loss accumulators

// Packed fp32x2 FMA (2 FMAs per issue slot on sm_100a)
__device__ __forceinline__ void ffma2(unsigned long long& d,
                                      unsigned long long a,
                                      unsigned long long b) {
    asm("fma.rn.f32x2 %0, %1, %2, %0;" : "+l"(d) : "l"(a), "l"(b));
}
// Duplicate a float into both lanes of an f32x2 register pair
__device__ __forceinline__ unsigned long long dup2(float x) {
    unsigned long long r;
    asm("mov.b64 %0, {%1, %1};" : "=l"(r) : "f"(x));
    return r;
}

// ---------------------------------------------------------------------------
// Prep: transpose codebooks [gq][k][c] -> [gq][c][k], code norms, zero commits
// ---------------------------------------------------------------------------
__global__ void prep_kernel(const float* __restrict__ cbsrc) {
    int idx = blockIdx.x * 256 + threadIdx.x;           // < 409600
    int gq = idx / (CD * NK);
    int rem = idx % (CD * NK);
    int c = rem / NK;
    int k = rem % NK;
    g_cbT[idx] = cbsrc[(size_t)gq * (NK * CD) + (size_t)k * CD + c];

    if (idx < NG * NQ * NK) {
        int gq2 = idx >> 10;
        int k2 = idx & (NK - 1);
        const float* p = cbsrc + ((size_t)gq2 * NK + k2) * CD;
        float s = 0.0f;
#pragma unroll 10
        for (int d = 0; d < CD; d++) s += p[d] * p[d];
        g_cc[idx] = s;
    }
    if (idx < NG * NQ) g_commit[idx] = 0.0f;
}

// ---------------------------------------------------------------------------
// Main RVQ kernel: block = 128 tokens x 1 group, 256 threads.
// Thread tile: 8 tokens x 16 codes (64 f32x2 accumulators).
// Shared layout (floats):
//   rS  [0,6400)      : residual [c 50][tok 128]           (25600 B)
//   qS  [6400,12800)  : selected-code sums [c 50][tok 128] (25600 B)
//   cbS [12800,25600) : codebook k-tile [c 50][k 256], SW128 swizzled (51200 B)
//                       (aliased at start: xS [tok 128][d 50] + WiS [2500];
//                        aliased at end: WoS [2500])
//   ccS [25600,25856) : ||cb||^2 for current k-tile        (1024 B)
// ---------------------------------------------------------------------------
#define SMEM_FLOATS 25856
#define SMEM_BYTES (SMEM_FLOATS * 4)

__global__ void __launch_bounds__(256, 1)
rvq_main(const float* __restrict__ x,
         const float* __restrict__ W_in,
         const float* __restrict__ b_in,
         const float* __restrict__ W_out,
         const float* __restrict__ b_out,
         float* __restrict__ out) {
    extern __shared__ float smem[];
    float* rS  = smem;
    float* qS  = smem + 6400;
    float* cbS = smem + 12800;
    float* ccS = smem + 25600;
    float* xS  = cbS;                 // alias (prologue only)
    float* WiS = cbS + 6400;          // alias (prologue only)
    float* WoS = cbS;                 // alias (epilogue only)
    char*  cbB = reinterpret_cast<char*>(cbS);

    const int tid = threadIdx.x;
    const int tx = tid & 15;          // 16 code-threads, 16 codes each
    const int ty = tid >> 4;          // 16 token-threads, 8 tokens each
    const int g = blockIdx.y;
    const int t0 = blockIdx.x * TILE_T;

    // ---- load x tile + W_in into smem ----
    for (int i = tid; i < TILE_T * DG; i += 256) {
        int tok = i / DG, d = i % DG;
        xS[i] = x[(size_t)(t0 + tok) * ND + g * DG + d];
    }
    for (int i = tid; i < DG * CD; i += 256)
        WiS[i] = W_in[g * DG * CD + i];
    __syncthreads();

    // ---- project_in: r = x @ W_in + b_in (thread: fixed tok, 25 c values) ----
    {
        int tok = tid & 127;
        float xrow[DG];
#pragma unroll 10
        for (int d = 0; d < DG; d++) xrow[d] = xS[tok * DG + d];
        for (int i = tid; i < TILE_T * CD; i += 256) {
            int c = i >> 7;
            float s = b_in[g * CD + c];
#pragma unroll 10
            for (int d = 0; d < DG; d++) s += xrow[d] * WiS[d * CD + c];
            rS[c * TILE_T + tok] = s;
            qS[c * TILE_T + tok] = 0.0f;
        }
    }

    // precompute swizzled byte offsets for this thread's 4 codebook chunks
    int swoff[4];
#pragma unroll
    for (int j = 0; j < 4; j++) {
        int o = tx * 64 + j * 16;
        swoff[j] = o ^ ((o >> 3) & 0x70);
    }
    int swfill;  // swizzled write offset for tile fill (kk = tid)
    {
        int o = (tid & 255) * 4;
        swfill = o ^ ((o >> 3) & 0x70);
    }

    const float* rp = rS + ty * 8;

    // ---- residual VQ stages ----
    for (int q = 0; q < NQ; q++) {
        const float* cbT = g_cbT + (size_t)(g * NQ + q) * (CD * NK);
        const float* ccG = g_cc + (g * NQ + q) * NK;

        float bestv[8];
        int   besti[8];
#pragma unroll
        for (int t = 0; t < 8; t++) { bestv[t] = __int_as_float(0x7f800000); besti[t] = 0; }

        for (int kt = 0; kt < NKT; kt++) {
            __syncthreads();   // prior cbS/ccS consumers done (also guards prologue aliases)
            // fill codebook tile (swizzled) + norms
            {
                const float* src = cbT + (kt << 8) + tid;
#pragma unroll 10
                for (int j = 0; j < CD; j++)
                    *reinterpret_cast<float*>(cbB + j * 1024 + swfill) = src[j * NK];
                ccS[tid] = ccG[(kt << 8) + tid];
            }
            __syncthreads();

            // register tile of code norms (16 codes = 8 pairs)
            unsigned long long ccn[8];
            {
                ulonglong2 a = *reinterpret_cast<const ulonglong2*>(ccS + tx * 16);
                ulonglong2 b = *reinterpret_cast<const ulonglong2*>(ccS + tx * 16 + 4);
                ulonglong2 c2 = *reinterpret_cast<const ulonglong2*>(ccS + tx * 16 + 8);
                ulonglong2 d2 = *reinterpret_cast<const ulonglong2*>(ccS + tx * 16 + 12);
                ccn[0] = a.x; ccn[1] = a.y; ccn[2] = b.x; ccn[3] = b.y;
                ccn[4] = c2.x; ccn[5] = c2.y; ccn[6] = d2.x; ccn[7] = d2.y;
            }

            unsigned long long acc[64];
#pragma unroll
            for (int i = 0; i < 64; i++) acc[i] = 0ULL;

#pragma unroll 2
            for (int c = 0; c < CD; c++) {
                float4 ra = *reinterpret_cast<const float4*>(rp + c * TILE_T);
                float4 rb = *reinterpret_cast<const float4*>(rp + c * TILE_T + 4);
                unsigned long long rr[8];
                rr[0] = dup2(ra.x); rr[1] = dup2(ra.y);
                rr[2] = dup2(ra.z); rr[3] = dup2(ra.w);
                rr[4] = dup2(rb.x); rr[5] = dup2(rb.y);
                rr[6] = dup2(rb.z); rr[7] = dup2(rb.w);

                unsigned long long cb[8];
                {
                    const char* rowp = cbB + c * 1024;
                    ulonglong2 v0 = *reinterpret_cast<const ulonglong2*>(rowp + swoff[0]);
                    ulonglong2 v1 = *reinterpret_cast<const ulonglong2*>(rowp + swoff[1]);
                    ulonglong2 v2 = *reinterpret_cast<const ulonglong2*>(rowp + swoff[2]);
                    ulonglong2 v3 = *reinterpret_cast<const ulonglong2*>(rowp + swoff[3]);
                    cb[0] = v0.x; cb[1] = v0.y; cb[2] = v1.x; cb[3] = v1.y;
                    cb[4] = v2.x; cb[5] = v2.y; cb[6] = v3.x; cb[7] = v3.y;
                }
#pragma unroll
                for (int t = 0; t < 8; t++) {
#pragma unroll
                    for (int p = 0; p < 8; p++) ffma2(acc[t * 8 + p], rr[t], cb[p]);
                }
            }

            // distances + running argmin (ascending k, strict < keeps first min)
#pragma unroll
            for (int t = 0; t < 8; t++) {
#pragma unroll
                for (int p = 0; p < 8; p++) {
                    float2 v = *reinterpret_cast<float2*>(&acc[t * 8 + p]);
                    float2 cn = *reinterpret_cast<float2*>(&ccn[p]);
                    int k0 = (kt << 8) + (tx << 4) + (p << 1);
                    float d0 = fmaf(-2.0f, v.x, cn.x);
                    float d1 = fmaf(-2.0f, v.y, cn.y);
                    if (d0 < bestv[t]) { bestv[t] = d0; besti[t] = k0; }
                    if (d1 < bestv[t]) { bestv[t] = d1; besti[t] = k0 + 1; }
                }
            }
        }

        // cross-lane argmin over the 16 tx lanes (lexicographic: first min wins)
#pragma unroll
        for (int off = 1; off < 16; off <<= 1) {
#pragma unroll
            for (int t = 0; t < 8; t++) {
                float ov = __shfl_xor_sync(0xffffffffu, bestv[t], off);
                int   oi = __shfl_xor_sync(0xffffffffu, besti[t], off);
                if (ov < bestv[t] || (ov == bestv[t] && oi < besti[t])) {
                    bestv[t] = ov; besti[t] = oi;
                }
            }
        }

        // residual update + commit accumulation (own tokens; c = tx + 16m)
        float clocal = 0.0f;
#pragma unroll
        for (int t = 0; t < 8; t++) {
            int tok = ty * 8 + t;
            int idx = besti[t];
            for (int c = tx; c < CD; c += 16) {
                float qv = cbT[c * NK + idx];
                float r = rS[c * TILE_T + tok];
                float dr = qv - r;
                clocal += dr * dr;
                rS[c * TILE_T + tok] = r - qv;
                qS[c * TILE_T + tok] += qv;
            }
        }
#pragma unroll
        for (int off = 16; off; off >>= 1)
            clocal += __shfl_down_sync(0xffffffffu, clocal, off);
        if ((tid & 31) == 0) atomicAdd(&g_commit[g * NQ + q], clocal);
    }

    __syncthreads();   // all qS writes done; cbS free for W_out

    for (int i = tid; i < CD * DG; i += 256)
        WoS[i] = W_out[g * CD * DG + i];
    __syncthreads();

    // ---- project_out: out = qsum @ W_out + b_out (thread: fixed tok) ----
    {
        int tok = tid & 127;
        for (int i = tid; i < TILE_T * DG; i += 256) {
            int dcol = i >> 7;
            float s = b_out[g * DG + dcol];
#pragma unroll 10
            for (int c = 0; c < CD; c++)
                s += qS[c * TILE_T + tok] * WoS[c * DG + dcol];
            out[(size_t)(t0 + tok) * ND + g * DG + dcol] = s;
        }
    }
}

// ---------------------------------------------------------------------------
// Finalize: recon_loss, loss, commit_losses scalar. Warp per token.
// ---------------------------------------------------------------------------
__global__ void __launch_bounds__(256)
finalize_kernel(const float* __restrict__ x, float* dst) {
    int w = (blockIdx.x * blockDim.x + threadIdx.x) >> 5;
    int lane = threadIdx.x & 31;

    float csum = 0.0f;
#pragma unroll
    for (int i = 0; i < NG * NQ; i++) csum += g_commit[i];
    float commit = csum * (1.0f / ((float)NTOK * (float)CD * (float)(NG * NQ)));

    if (w < NTOK) {
        const float* xr = x + (size_t)w * ND;
        const float* qr = dst + OFF_QUANT + (size_t)w * ND;
        float s = 0.0f;
        for (int d = lane; d < ND; d += 32) {
            float df = xr[d] - qr[d];
            s += df * df;
        }
#pragma unroll
        for (int off = 16; off; off >>= 1)
            s += __shfl_down_sync(0xffffffffu, s, off);
        if (lane == 0) {
            float recon = s * (1.0f / (float)ND);
            dst[OFF_RECON + w] = recon;
            dst[OFF_LOSS + w] = recon + commit;
        }
    }
    if (blockIdx.x == 0 && threadIdx.x == 0) dst[OFF_COMMIT] = commit;
}

// ---------------------------------------------------------------------------
extern "C" void kernel_launch(void* const* d_in, const int* in_sizes, int n_in,
                              void* d_out, int out_size) {
    const float* x      = (const float*)d_in[0];
    const float* W_in   = (const float*)d_in[1];
    const float* b_in   = (const float*)d_in[2];
    const float* W_out  = (const float*)d_in[3];
    const float* b_out  = (const float*)d_in[4];
    const float* cbooks = (const float*)d_in[5];
    float* out = (float*)d_out;

    cudaFuncSetAttribute(rvq_main, cudaFuncAttributeMaxDynamicSharedMemorySize,
                         SMEM_BYTES);

    prep_kernel<<<(NG * NQ * CD * NK) / 256, 256>>>(cbooks);
    rvq_main<<<dim3(NTILES, NG), 256, SMEM_BYTES>>>(x, W_in, b_in, W_out, b_out, out);
    finalize_kernel<<<(NTOK * 32) / 256, 256>>>(x, out);
}